// round 12
// baseline (speedup 1.0000x reference)
#include <cuda_runtime.h>
#include <cuda_fp16.h>
#include <cstdint>

// ---------------------------------------------------------------------------
// GCN via mma.sync fp16 GEMMs (fp32 accumulate).
//   GEMM1: H^T[256][32768] = W^T @ X^T  -> fp16
//   GEMM2: Out[b] = adj @ H_b           -> fp32
// R12: tile-pairing — each CTA runs 2 output tiles through one continuous
//      cp.async ring (no pipeline drain between tiles); grids halve to one
//      wave at 2 CTAs/SM. cvt_all = R8 version.
// ---------------------------------------------------------------------------

#define N_NODES 512
#define N_BATCH 64
#define D_IN    256
#define D_OUT   256
#define M_ALL   (N_NODES * N_BATCH)   // 32768

#define BM 128
#define BN 128
#define BKB 64                        // fp16 k per stage
#define NTHREADS 256
#define S_STAGES 3
#define PITCHB 144                    // 128B row + 16B pad -> ldsm conflict-free
#define TILEB (128 * PITCHB)          // 18432 per matrix
#define STAGEB (2 * TILEB)            // 36864
#define SMEM_TOTAL (S_STAGES * STAGEB) // 110592
#define OFF_A 0
#define OFF_B TILEB

// device scratch
__device__ __half g_xh[(size_t)M_ALL * D_IN];
__device__ __half g_wth[D_OUT * D_IN];
__device__ __half g_adjh[N_NODES * N_NODES];
__device__ __half g_h[(size_t)D_OUT * M_ALL];

// ---------------- helpers ----------------
__device__ __forceinline__ uint32_t smem_u32(const void* p) {
    uint32_t a;
    asm("{ .reg .u64 t; cvta.to.shared.u64 t, %1; cvt.u32.u64 %0, t; }" : "=r"(a) : "l"(p));
    return a;
}
__device__ __forceinline__ void cp16(uint32_t dst, const void* src) {
    asm volatile("cp.async.cg.shared.global [%0], [%1], 16;" :: "r"(dst), "l"(src) : "memory");
}
__device__ __forceinline__ void cp_commit() {
    asm volatile("cp.async.commit_group;" ::: "memory");
}
template <int N>
__device__ __forceinline__ void cp_wait() {
    asm volatile("cp.async.wait_group %0;" :: "n"(N) : "memory");
}
__device__ __forceinline__ void ldsm_x4(uint32_t* r, uint32_t addr) {
    asm volatile("ldmatrix.sync.aligned.m8n8.x4.shared.b16 {%0,%1,%2,%3}, [%4];"
                 : "=r"(r[0]), "=r"(r[1]), "=r"(r[2]), "=r"(r[3]) : "r"(addr));
}
__device__ __forceinline__ void mma_f16(float* c, const uint32_t* a, const uint32_t* b) {
    asm volatile(
        "mma.sync.aligned.m16n8k16.row.col.f32.f16.f16.f32 "
        "{%0,%1,%2,%3}, {%4,%5,%6,%7}, {%8,%9}, {%0,%1,%2,%3};"
        : "+f"(c[0]), "+f"(c[1]), "+f"(c[2]), "+f"(c[3])
        : "r"(a[0]), "r"(a[1]), "r"(a[2]), "r"(a[3]), "r"(b[0]), "r"(b[1]));
}

// ---------------- merged convert kernel (R8 version) ----------------
// blocks [0,512): x cvt | [512,528): adj cvt | [528,784): w transpose cvt
__global__ __launch_bounds__(256) void cvt_all(const float* __restrict__ x,
                                               const float* __restrict__ adj,
                                               const float* __restrict__ w,
                                               __half* __restrict__ xh,
                                               __half* __restrict__ adjh,
                                               __half* __restrict__ wth) {
    const int b = blockIdx.x;
    if (b < 512) {
        const int n8 = M_ALL * D_IN / 8;   // 1048576
        int i = b * 256 + threadIdx.x;
        const int stride = 512 * 256;
        for (; i < n8; i += stride) {
            float4 a = ((const float4*)x)[2 * i];
            float4 c = ((const float4*)x)[2 * i + 1];
            __half2 h0 = __float22half2_rn(make_float2(a.x, a.y));
            __half2 h1 = __float22half2_rn(make_float2(a.z, a.w));
            __half2 h2 = __float22half2_rn(make_float2(c.x, c.y));
            __half2 h3 = __float22half2_rn(make_float2(c.z, c.w));
            uint4 v = {*(uint32_t*)&h0, *(uint32_t*)&h1, *(uint32_t*)&h2, *(uint32_t*)&h3};
            ((uint4*)xh)[i] = v;
        }
    } else if (b < 528) {
        const int n8 = N_NODES * N_NODES / 8;  // 32768
        int i = (b - 512) * 256 + threadIdx.x;
        const int stride = 16 * 256;
        for (; i < n8; i += stride) {
            float4 a = ((const float4*)adj)[2 * i];
            float4 c = ((const float4*)adj)[2 * i + 1];
            __half2 h0 = __float22half2_rn(make_float2(a.x, a.y));
            __half2 h1 = __float22half2_rn(make_float2(a.z, a.w));
            __half2 h2 = __float22half2_rn(make_float2(c.x, c.y));
            __half2 h3 = __float22half2_rn(make_float2(c.z, c.w));
            uint4 v = {*(uint32_t*)&h0, *(uint32_t*)&h1, *(uint32_t*)&h2, *(uint32_t*)&h3};
            ((uint4*)adjh)[i] = v;
        }
    } else {
        int o = b - 528;            // 0..255
        int i = threadIdx.x;        // 0..255
        wth[o * D_IN + i] = __float2half_rn(w[i * D_OUT + o]);
    }
}

// ---------------- main GEMM: C = A * B^T (both K-major, fp16) ----------------
// Each CTA processes `ntile` output tiles through one continuous pipeline.
// Per tile: B advances by tileB elements, C by tileC elements. A restarts at
// k=0 each tile (re-read; L2-resident).
template <bool HALF_OUT>
__global__ __launch_bounds__(NTHREADS, 2)
void hgemm_f16(const __half* __restrict__ A, int lda,
               const __half* __restrict__ B, int ldb,
               int n0_mult, long zB, long zC,
               __half* __restrict__ Ch, float* __restrict__ Cf,
               int ldc, int K, long tileB, long tileC, int ntile) {
    extern __shared__ char smem[];
    const uint32_t sb = smem_u32(smem);
    const int tid = threadIdx.x;
    const int lane = tid & 31;
    const int wid = tid >> 5;
    const int wm = (wid & 3) * 32;   // warp m offset
    const int wn = (wid >> 2) * 64;  // warp n offset

    const int m0 = blockIdx.y * BM;
    const int n0 = blockIdx.x * n0_mult;
    B  += (long)blockIdx.z * zB + (size_t)n0 * ldb;
    Cf += (long)blockIdx.z * zC;

    // cp.async coords: per matrix 128 rows x 8 chunks of 16B; 4 chunks/thread
    const int cr = tid >> 3;          // base row 0..31 (+32 per j)
    const int cc = tid & 7;           // 16B chunk in row
    const uint32_t soBase = (uint32_t)(cc * 16);
    const int gcol = cc * 8;          // halves

    // ldmatrix addresses (conflict-free: PITCHB mod 128 = 16)
    const uint32_t aOff = (uint32_t)((wm + (lane & 15)) * PITCHB + ((lane >> 4) << 4));
    const uint32_t bOff = (uint32_t)((wn + ((lane >> 4) << 3) + (lane & 7)) * PITCHB +
                                     (((lane >> 3) & 1) << 4));

    float acc[2][8][4];
#pragma unroll
    for (int mt = 0; mt < 2; mt++)
#pragma unroll
        for (int nt = 0; nt < 8; nt++)
#pragma unroll
            for (int q = 0; q < 4; q++) acc[mt][nt][q] = 0.0f;

    const int NTin = K / BKB;         // inner stages per tile
    const int NS = NTin * ntile;      // total stages

    auto load_stage = [&](int s) {
        const int tile = s / NTin;
        const int t = s - tile * NTin;
        const uint32_t st = sb + (uint32_t)((s % S_STAGES) * STAGEB);
        const int k0 = t * BKB + gcol;
        const __half* Bt = B + (long)tile * tileB;
#pragma unroll
        for (int j = 0; j < 4; j++) {
            int r = cr + j * 32;
            uint32_t so = (uint32_t)(r * PITCHB) + soBase;
            cp16(st + OFF_A + so, A + (size_t)(m0 + r) * lda + k0);
            cp16(st + OFF_B + so, Bt + (size_t)r * ldb + k0);
        }
        cp_commit();
    };

    load_stage(0);
    if (NS > 1) load_stage(1);

    const int l4 = lane >> 2;
    const int lp = lane & 3;

    for (int s = 0; s < NS; s++) {
        cp_wait<1>();
        __syncthreads();

        // prefetch stage s+2 into slot (s+2)%3 == slot of stage s-1 (fully
        // consumed). Commit every iteration to keep wait_group<1> aligned.
        if (s + 2 < NS) {
            load_stage(s + 2);
        } else {
            cp_commit();
        }

        const uint32_t st = sb + (uint32_t)((s % S_STAGES) * STAGEB);

        // A-frag double buffer across ko
        uint32_t ah[2][2][4];
#pragma unroll
        for (int mt = 0; mt < 2; mt++)
            ldsm_x4(ah[0][mt], st + OFF_A + aOff + mt * 16 * PITCHB);

#pragma unroll
        for (int ko = 0; ko < 4; ko++) {
            const int cur = ko & 1, nxt = cur ^ 1;
            if (ko < 3) {
#pragma unroll
                for (int mt = 0; mt < 2; mt++)
                    ldsm_x4(ah[nxt][mt], st + OFF_A + aOff + mt * 16 * PITCHB + (ko + 1) * 32);
            }
#pragma unroll
            for (int np = 0; np < 4; np++) {
                uint32_t bh[4];
                ldsm_x4(bh, st + OFF_B + bOff + np * 16 * PITCHB + ko * 32);
#pragma unroll
                for (int sub = 0; sub < 2; sub++)
#pragma unroll
                    for (int mt = 0; mt < 2; mt++)
                        mma_f16(acc[mt][np * 2 + sub], ah[cur][mt], bh + sub * 2);
            }
        }

        // tile boundary: flush accumulators, reset
        const int tile = s / NTin;
        if (s - tile * NTin == NTin - 1) {
#pragma unroll
            for (int mt = 0; mt < 2; mt++) {
#pragma unroll
                for (int nt = 0; nt < 8; nt++) {
                    float* c = acc[mt][nt];
                    long m = m0 + wm + mt * 16 + l4;
                    long n = n0 + wn + nt * 8 + lp * 2;
                    if (HALF_OUT) {
                        __half* dst = Ch + (long)tile * tileC;
                        __half2 p0 = __float22half2_rn(make_float2(c[0], c[1]));
                        __half2 p1 = __float22half2_rn(make_float2(c[2], c[3]));
                        *(uint32_t*)(dst + m * ldc + n) = *(uint32_t*)&p0;
                        *(uint32_t*)(dst + (m + 8) * ldc + n) = *(uint32_t*)&p1;
                    } else {
                        float* dst = Cf + (long)tile * tileC;
                        *(float2*)(dst + m * ldc + n) = make_float2(c[0], c[1]);
                        *(float2*)(dst + (m + 8) * ldc + n) = make_float2(c[2], c[3]);
                    }
                    c[0] = c[1] = c[2] = c[3] = 0.0f;
                }
            }
        }
    }
}

// ---------------- launch ----------------
extern "C" void kernel_launch(void* const* d_in, const int* in_sizes, int n_in,
                              void* d_out, int out_size) {
    const float* x      = (const float*)d_in[0];
    const float* weight = (const float*)d_in[2];
    const float* adj    = (const float*)d_in[3];
    float* out          = (float*)d_out;

    __half *xh, *wth, *adjh, *h;
    cudaGetSymbolAddress((void**)&xh, g_xh);
    cudaGetSymbolAddress((void**)&wth, g_wth);
    cudaGetSymbolAddress((void**)&adjh, g_adjh);
    cudaGetSymbolAddress((void**)&h, g_h);

    cudaFuncSetAttribute(hgemm_f16<true>, cudaFuncAttributeMaxDynamicSharedMemorySize, SMEM_TOTAL);
    cudaFuncSetAttribute(hgemm_f16<false>, cudaFuncAttributeMaxDynamicSharedMemorySize, SMEM_TOTAL);

    cvt_all<<<784, 256>>>(x, adj, weight, xh, adjh, wth);

    // GEMM1: H^T = W^T @ X^T ; A=W^T [256][256], B=X [32768][256] -> H^T fp16
    // Each CTA: 2 adjacent n-tiles (n0_mult=256, tileB=128*ldb, tileC=128).
    {
        dim3 grid(M_ALL / (BN * 2), D_OUT / BM, 1);   // (128, 2, 1)
        hgemm_f16<true><<<grid, NTHREADS, SMEM_TOTAL>>>(
            wth, D_IN,
            xh, D_IN,
            BN * 2, 0L, 0L,
            h, nullptr, M_ALL,
            D_IN, (long)BN * D_IN, (long)BN, 2);
    }
    // GEMM2: Out[b] = adj @ H_b ; A=adj [512][512], B=H^T col-slice b*512
    // Each CTA: 2 adjacent batches (zB=2*512, zC=2*131072, tileB=512).
    {
        dim3 grid(D_OUT / BN, N_NODES / BM, N_BATCH / 2);   // (2, 4, 32)
        hgemm_f16<false><<<grid, NTHREADS, SMEM_TOTAL>>>(
            adjh, N_NODES,
            h, M_ALL,
            BN, 2L * N_NODES, 2L * (N_NODES * D_OUT),
            nullptr, out, D_OUT,
            N_NODES, (long)N_NODES, (long)(N_NODES * D_OUT), 2);
    }
}

// round 13
// speedup vs baseline: 1.1464x; 1.1464x over previous
#include <cuda_runtime.h>
#include <cuda_fp16.h>
#include <cstdint>

// ---------------------------------------------------------------------------
// GCN via mma.sync fp16 GEMMs (fp32 accumulate).
//   GEMM1: H^T[256][32768] = W^T @ X^T  -> fp16
//   GEMM2: Out[b] = adj @ H_b           -> fp32
// R13: GEMMs identical to R8 (measured optimum, ~85% of mma.sync issue
//      floor). cvt rewritten as flat one-shot MLP=4 streaming kernel.
// ---------------------------------------------------------------------------

#define N_NODES 512
#define N_BATCH 64
#define D_IN    256
#define D_OUT   256
#define M_ALL   (N_NODES * N_BATCH)   // 32768

#define BM 128
#define BN 128
#define BKB 64                        // fp16 k per stage
#define NTHREADS 256
#define S_STAGES 3
#define PITCHB 144                    // 128B row + 16B pad -> ldsm conflict-free
#define TILEB (128 * PITCHB)          // 18432 per matrix
#define STAGEB (2 * TILEB)            // 36864
#define SMEM_TOTAL (S_STAGES * STAGEB) // 110592
#define OFF_A 0
#define OFF_B TILEB

// device scratch
__device__ __half g_xh[(size_t)M_ALL * D_IN];
__device__ __half g_wth[D_OUT * D_IN];
__device__ __half g_adjh[N_NODES * N_NODES];
__device__ __half g_h[(size_t)D_OUT * M_ALL];

// ---------------- helpers ----------------
__device__ __forceinline__ uint32_t smem_u32(const void* p) {
    uint32_t a;
    asm("{ .reg .u64 t; cvta.to.shared.u64 t, %1; cvt.u32.u64 %0, t; }" : "=r"(a) : "l"(p));
    return a;
}
__device__ __forceinline__ void cp16(uint32_t dst, const void* src) {
    asm volatile("cp.async.cg.shared.global [%0], [%1], 16;" :: "r"(dst), "l"(src) : "memory");
}
__device__ __forceinline__ void cp_commit() {
    asm volatile("cp.async.commit_group;" ::: "memory");
}
template <int N>
__device__ __forceinline__ void cp_wait() {
    asm volatile("cp.async.wait_group %0;" :: "n"(N) : "memory");
}
__device__ __forceinline__ void ldsm_x4(uint32_t* r, uint32_t addr) {
    asm volatile("ldmatrix.sync.aligned.m8n8.x4.shared.b16 {%0,%1,%2,%3}, [%4];"
                 : "=r"(r[0]), "=r"(r[1]), "=r"(r[2]), "=r"(r[3]) : "r"(addr));
}
__device__ __forceinline__ void mma_f16(float* c, const uint32_t* a, const uint32_t* b) {
    asm volatile(
        "mma.sync.aligned.m16n8k16.row.col.f32.f16.f16.f32 "
        "{%0,%1,%2,%3}, {%4,%5,%6,%7}, {%8,%9}, {%0,%1,%2,%3};"
        : "+f"(c[0]), "+f"(c[1]), "+f"(c[2]), "+f"(c[3])
        : "r"(a[0]), "r"(a[1]), "r"(a[2]), "r"(a[3]), "r"(b[0]), "r"(b[1]));
}
__device__ __forceinline__ uint2 cvt_f4(float4 a) {
    __half2 h0 = __float22half2_rn(make_float2(a.x, a.y));
    __half2 h1 = __float22half2_rn(make_float2(a.z, a.w));
    return make_uint2(*(uint32_t*)&h0, *(uint32_t*)&h1);
}

// ---------------- convert kernel (flat, one-shot, MLP=4) ----------------
// blocks [0,2048): x (2048*256 threads x 4 float4 = 2097152 float4 = 32MB)
// blocks [2048,2112): adj (64*256 threads x 4 float4 = 65536 float4)
// blocks [2112,2368): w transpose (256x256)
__global__ __launch_bounds__(256) void cvt_all(const float* __restrict__ x,
                                               const float* __restrict__ adj,
                                               const float* __restrict__ w,
                                               __half* __restrict__ xh,
                                               __half* __restrict__ adjh,
                                               __half* __restrict__ wth) {
    const int b = blockIdx.x;
    if (b < 2048) {
        const size_t t = (size_t)b * 256 + threadIdx.x;
        const float4* src = (const float4*)x + t * 4;
        float4 v0 = src[0], v1 = src[1], v2 = src[2], v3 = src[3];
        uint2 a0 = cvt_f4(v0), a1 = cvt_f4(v1), a2 = cvt_f4(v2), a3 = cvt_f4(v3);
        uint4* dst = (uint4*)xh + t * 2;
        dst[0] = make_uint4(a0.x, a0.y, a1.x, a1.y);
        dst[1] = make_uint4(a2.x, a2.y, a3.x, a3.y);
    } else if (b < 2112) {
        const size_t t = (size_t)(b - 2048) * 256 + threadIdx.x;
        const float4* src = (const float4*)adj + t * 4;
        float4 v0 = src[0], v1 = src[1], v2 = src[2], v3 = src[3];
        uint2 a0 = cvt_f4(v0), a1 = cvt_f4(v1), a2 = cvt_f4(v2), a3 = cvt_f4(v3);
        uint4* dst = (uint4*)adjh + t * 2;
        dst[0] = make_uint4(a0.x, a0.y, a1.x, a1.y);
        dst[1] = make_uint4(a2.x, a2.y, a3.x, a3.y);
    } else {
        int o = b - 2112;           // 0..255
        int i = threadIdx.x;        // 0..255
        wth[o * D_IN + i] = __float2half_rn(w[i * D_OUT + o]);
    }
}

// ---------------- main GEMM: C = A * B^T (both K-major, fp16) ----------------
// (identical to R8 — measured optimum)
template <bool HALF_OUT>
__global__ __launch_bounds__(NTHREADS, 2)
void hgemm_f16(const __half* __restrict__ A, int lda,
               const __half* __restrict__ B, int ldb, long bStride,
               __half* __restrict__ Ch, float* __restrict__ Cf,
               int ldc, long cStride, int K) {
    extern __shared__ char smem[];
    const uint32_t sb = smem_u32(smem);
    const int tid = threadIdx.x;
    const int lane = tid & 31;
    const int wid = tid >> 5;
    const int wm = (wid & 3) * 32;   // warp m offset
    const int wn = (wid >> 2) * 64;  // warp n offset

    const int m0 = blockIdx.y * BM;
    const int n0 = blockIdx.x * BN;
    const long bz = blockIdx.z;
    B += bz * bStride;

    // cp.async coords: per matrix 128 rows x 8 chunks of 16B; 4 chunks/thread
    const int cr = tid >> 3;          // base row 0..31 (+32 per j)
    const int cc = tid & 7;           // 16B chunk in row
    const uint32_t soBase = (uint32_t)(cc * 16);
    const int gcol = cc * 8;          // halves

    // ldmatrix addresses (conflict-free: PITCHB mod 128 = 16)
    const uint32_t aOff = (uint32_t)((wm + (lane & 15)) * PITCHB + ((lane >> 4) << 4));
    const uint32_t bOff = (uint32_t)((wn + ((lane >> 4) << 3) + (lane & 7)) * PITCHB +
                                     (((lane >> 3) & 1) << 4));

    float acc[2][8][4];
#pragma unroll
    for (int mt = 0; mt < 2; mt++)
#pragma unroll
        for (int nt = 0; nt < 8; nt++)
#pragma unroll
            for (int q = 0; q < 4; q++) acc[mt][nt][q] = 0.0f;

    const int NT = K / BKB;

    auto load_stage = [&](int t) {
        const uint32_t st = sb + (uint32_t)((t % S_STAGES) * STAGEB);
        const int k0 = t * BKB + gcol;
#pragma unroll
        for (int j = 0; j < 4; j++) {
            int r = cr + j * 32;
            uint32_t so = (uint32_t)(r * PITCHB) + soBase;
            cp16(st + OFF_A + so, A + (size_t)(m0 + r) * lda + k0);
            cp16(st + OFF_B + so, B + (size_t)(n0 + r) * ldb + k0);
        }
        cp_commit();
    };

    load_stage(0);
    if (NT > 1) load_stage(1);

    for (int t = 0; t < NT; t++) {
        cp_wait<1>();
        __syncthreads();

        const uint32_t st = sb + (uint32_t)((t % S_STAGES) * STAGEB);

        // A-frag double buffer across ko
        uint32_t ah[2][2][4];
#pragma unroll
        for (int mt = 0; mt < 2; mt++)
            ldsm_x4(ah[0][mt], st + OFF_A + aOff + mt * 16 * PITCHB);

#pragma unroll
        for (int ko = 0; ko < 4; ko++) {
            const int cur = ko & 1, nxt = cur ^ 1;
            if (ko < 3) {
#pragma unroll
                for (int mt = 0; mt < 2; mt++)
                    ldsm_x4(ah[nxt][mt], st + OFF_A + aOff + mt * 16 * PITCHB + (ko + 1) * 32);
            }
#pragma unroll
            for (int np = 0; np < 4; np++) {
                uint32_t bh[4];
                ldsm_x4(bh, st + OFF_B + bOff + np * 16 * PITCHB + ko * 32);
#pragma unroll
                for (int sub = 0; sub < 2; sub++)
#pragma unroll
                    for (int mt = 0; mt < 2; mt++)
                        mma_f16(acc[mt][np * 2 + sub], ah[cur][mt], bh + sub * 2);
            }
        }

        __syncthreads();
        // Commit every iteration so cp_wait<1> at iteration t implies stage t done.
        if (t + 2 < NT) {
            load_stage(t + 2);
        } else {
            cp_commit();
        }
    }

    // epilogue
    const int l4 = lane >> 2;
    const int lp = lane & 3;
#pragma unroll
    for (int mt = 0; mt < 2; mt++) {
#pragma unroll
        for (int nt = 0; nt < 8; nt++) {
            const float* c = acc[mt][nt];
            long m = m0 + wm + mt * 16 + l4;
            long n = n0 + wn + nt * 8 + lp * 2;
            if (HALF_OUT) {
                __half2 p0 = __float22half2_rn(make_float2(c[0], c[1]));
                __half2 p1 = __float22half2_rn(make_float2(c[2], c[3]));
                *(uint32_t*)(Ch + m * ldc + n) = *(uint32_t*)&p0;
                *(uint32_t*)(Ch + (m + 8) * ldc + n) = *(uint32_t*)&p1;
            } else {
                float* base = Cf + bz * cStride;
                *(float2*)(base + m * ldc + n) = make_float2(c[0], c[1]);
                *(float2*)(base + (m + 8) * ldc + n) = make_float2(c[2], c[3]);
            }
        }
    }
}

// ---------------- launch ----------------
extern "C" void kernel_launch(void* const* d_in, const int* in_sizes, int n_in,
                              void* d_out, int out_size) {
    const float* x      = (const float*)d_in[0];
    const float* weight = (const float*)d_in[2];
    const float* adj    = (const float*)d_in[3];
    float* out          = (float*)d_out;

    __half *xh, *wth, *adjh, *h;
    cudaGetSymbolAddress((void**)&xh, g_xh);
    cudaGetSymbolAddress((void**)&wth, g_wth);
    cudaGetSymbolAddress((void**)&adjh, g_adjh);
    cudaGetSymbolAddress((void**)&h, g_h);

    cudaFuncSetAttribute(hgemm_f16<true>, cudaFuncAttributeMaxDynamicSharedMemorySize, SMEM_TOTAL);
    cudaFuncSetAttribute(hgemm_f16<false>, cudaFuncAttributeMaxDynamicSharedMemorySize, SMEM_TOTAL);

    cvt_all<<<2368, 256>>>(x, adj, weight, xh, adjh, wth);

    // GEMM1: H^T = W^T @ X^T ; A=W^T [256][256], B=X [32768][256] -> H^T fp16
    {
        dim3 grid(M_ALL / BN, D_OUT / BM, 1);
        hgemm_f16<true><<<grid, NTHREADS, SMEM_TOTAL>>>(
            wth, D_IN,
            xh, D_IN, 0L,
            h, nullptr, M_ALL, 0L,
            D_IN);
    }
    // GEMM2: Out[b] = adj @ H_b ; A=adj [512][512], B=H^T col-slice b*512
    {
        dim3 grid(D_OUT / BN, N_NODES / BM, N_BATCH);
        hgemm_f16<false><<<grid, NTHREADS, SMEM_TOTAL>>>(
            adjh, N_NODES,
            h, M_ALL, (long)N_NODES,
            nullptr, out, D_OUT, (long)(N_NODES * D_OUT),
            N_NODES);
    }
}

// round 14
// speedup vs baseline: 1.1539x; 1.0065x over previous
#include <cuda_runtime.h>
#include <cuda_fp16.h>
#include <cstdint>

// ---------------------------------------------------------------------------
// GCN via mma.sync fp16 GEMMs (fp32 accumulate).
//   GEMM1 (fused cvt): H^T = W^T @ X^T, X read as fp32 via cp.async ring and
//                      converted fp32->fp16 in smem. -> H^T fp16
//   GEMM2: Out[b] = adj @ H_b  (R8 kernel, unchanged) -> fp32
// R14: removes the separate 10.5us x-convert phase entirely.
// ---------------------------------------------------------------------------

#define N_NODES 512
#define N_BATCH 64
#define D_IN    256
#define D_OUT   256
#define M_ALL   (N_NODES * N_BATCH)   // 32768

// ---- GEMM2 (R8) config ----
#define BM 128
#define BN 128
#define BKB 64
#define NTHREADS 256
#define S_STAGES 3
#define PITCHB 144
#define TILEB (128 * PITCHB)
#define STAGEB (2 * TILEB)
#define SMEM_TOTAL (S_STAGES * STAGEB) // 110592
#define OFF_A 0
#define OFF_B TILEB

// ---- GEMM1 fused config (BK=32 fp16) ----
#define G1_PITCH_A   80                   // 64B fp16 + 16 pad
#define G1_PITCH_B32 144                  // 128B fp32 + 16 pad
#define G1_A_STAGE   (128 * G1_PITCH_A)   // 10240
#define G1_B32_STAGE (128 * G1_PITCH_B32) // 18432
#define G1_OFF_A     0
#define G1_OFF_B32   (3 * G1_A_STAGE)                    // 30720
#define G1_OFF_B16   (G1_OFF_B32 + 3 * G1_B32_STAGE)     // 86016
#define G1_SMEM      (G1_OFF_B16 + 2 * G1_A_STAGE)       // 106496

// device scratch
__device__ __half g_wth[D_OUT * D_IN];
__device__ __half g_adjh[N_NODES * N_NODES];
__device__ __half g_h[(size_t)D_OUT * M_ALL];

// ---------------- helpers ----------------
__device__ __forceinline__ uint32_t smem_u32(const void* p) {
    uint32_t a;
    asm("{ .reg .u64 t; cvta.to.shared.u64 t, %1; cvt.u32.u64 %0, t; }" : "=r"(a) : "l"(p));
    return a;
}
__device__ __forceinline__ void cp16(uint32_t dst, const void* src) {
    asm volatile("cp.async.cg.shared.global [%0], [%1], 16;" :: "r"(dst), "l"(src) : "memory");
}
__device__ __forceinline__ void cp_commit() {
    asm volatile("cp.async.commit_group;" ::: "memory");
}
template <int N>
__device__ __forceinline__ void cp_wait() {
    asm volatile("cp.async.wait_group %0;" :: "n"(N) : "memory");
}
__device__ __forceinline__ void ldsm_x4(uint32_t* r, uint32_t addr) {
    asm volatile("ldmatrix.sync.aligned.m8n8.x4.shared.b16 {%0,%1,%2,%3}, [%4];"
                 : "=r"(r[0]), "=r"(r[1]), "=r"(r[2]), "=r"(r[3]) : "r"(addr));
}
__device__ __forceinline__ void mma_f16(float* c, const uint32_t* a, const uint32_t* b) {
    asm volatile(
        "mma.sync.aligned.m16n8k16.row.col.f32.f16.f16.f32 "
        "{%0,%1,%2,%3}, {%4,%5,%6,%7}, {%8,%9}, {%0,%1,%2,%3};"
        : "+f"(c[0]), "+f"(c[1]), "+f"(c[2]), "+f"(c[3])
        : "r"(a[0]), "r"(a[1]), "r"(a[2]), "r"(a[3]), "r"(b[0]), "r"(b[1]));
}
__device__ __forceinline__ uint2 cvt_f4(float4 a) {
    __half2 h0 = __float22half2_rn(make_float2(a.x, a.y));
    __half2 h1 = __float22half2_rn(make_float2(a.z, a.w));
    return make_uint2(*(uint32_t*)&h0, *(uint32_t*)&h1);
}

// ---------------- small convert kernel: adj + w^T ----------------
// blocks [0,64): adj (flat MLP=4) | [64,320): w transpose
__global__ __launch_bounds__(256) void cvt_small(const float* __restrict__ adj,
                                                 const float* __restrict__ w,
                                                 __half* __restrict__ adjh,
                                                 __half* __restrict__ wth) {
    const int b = blockIdx.x;
    if (b < 64) {
        const size_t t = (size_t)b * 256 + threadIdx.x;
        const float4* src = (const float4*)adj + t * 4;
        float4 v0 = src[0], v1 = src[1], v2 = src[2], v3 = src[3];
        uint2 a0 = cvt_f4(v0), a1 = cvt_f4(v1), a2 = cvt_f4(v2), a3 = cvt_f4(v3);
        uint4* dst = (uint4*)adjh + t * 2;
        dst[0] = make_uint4(a0.x, a0.y, a1.x, a1.y);
        dst[1] = make_uint4(a2.x, a2.y, a3.x, a3.y);
    } else {
        int o = b - 64;             // 0..255
        int i = threadIdx.x;        // 0..255
        wth[o * D_IN + i] = __float2half_rn(w[i * D_OUT + o]);
    }
}

// ---------------- GEMM1 fused: H^T = W^T @ X^T, X fp32 in-flight ----------
// C[m=dout][n=node] ; A = wth [256][256] fp16 K-major ; B = X [32768][256] f32.
// BK=32 fp16 per stage, 8 stages. B arrives fp32 via cp.async, converted in
// smem to a double-buffered fp16 region before each stage's MMAs.
__global__ __launch_bounds__(NTHREADS, 2)
void gemm1_fused(const __half* __restrict__ A,
                 const float* __restrict__ X,
                 __half* __restrict__ Ch) {
    extern __shared__ char smem[];
    const uint32_t sb = smem_u32(smem);
    const int tid = threadIdx.x;
    const int lane = tid & 31;
    const int wid = tid >> 5;
    const int wm = (wid & 3) * 32;   // warp m offset
    const int wn = (wid >> 2) * 64;  // warp n offset

    const int m0 = blockIdx.y * BM;  // dout tile (0,128)
    const int n0 = blockIdx.x * BN;  // node tile

    // A cp.async map: 128 rows x 4 chunks16B; 2 chunks/thread
    const int arow = tid >> 2;            // 0..63 (+64)
    const int acol = tid & 3;             // chunk in row
    // B fp32 cp.async map: 128 rows x 8 chunks16B; 4 chunks/thread
    const int brow = tid >> 3;            // 0..31 (+32*j)
    const int bcol = tid & 7;

    // convert map: 128 rows x 4 out-chunks16B; 2/thread
    const int vrow = tid >> 1;            // 0..127
    const int vcol = (tid & 1) * 2;       // out chunk base {0,2}

    // ldmatrix addresses (pitch 80)
    const uint32_t aOff = (uint32_t)((wm + (lane & 15)) * G1_PITCH_A + ((lane >> 4) << 4));
    const uint32_t bOff = (uint32_t)((wn + ((lane >> 4) << 3) + (lane & 7)) * G1_PITCH_A +
                                     (((lane >> 3) & 1) << 4));

    float acc[2][8][4];
#pragma unroll
    for (int mt = 0; mt < 2; mt++)
#pragma unroll
        for (int nt = 0; nt < 8; nt++)
#pragma unroll
            for (int q = 0; q < 4; q++) acc[mt][nt][q] = 0.0f;

    const int NT = D_IN / 32;   // 8 stages

    auto load_stage = [&](int s) {
        const uint32_t stA = sb + G1_OFF_A + (uint32_t)((s % 3) * G1_A_STAGE);
        const uint32_t stB = sb + G1_OFF_B32 + (uint32_t)((s % 3) * G1_B32_STAGE);
        const int k16 = s * 32;           // fp16 col base
#pragma unroll
        for (int j = 0; j < 2; j++) {
            int r = arow + j * 64;
            cp16(stA + (uint32_t)(r * G1_PITCH_A + acol * 16),
                 A + (size_t)(m0 + r) * D_IN + k16 + acol * 8);
        }
#pragma unroll
        for (int j = 0; j < 4; j++) {
            int r = brow + j * 32;
            cp16(stB + (uint32_t)(r * G1_PITCH_B32 + bcol * 16),
                 X + (size_t)(n0 + r) * D_IN + k16 + bcol * 4);
        }
        cp_commit();
    };

    load_stage(0);
    load_stage(1);

    for (int t = 0; t < NT; t++) {
        cp_wait<1>();
        __syncthreads();

        // convert stage t: Bf32[t%3] -> Bf16[t&1]
        const uint32_t srcB = sb + G1_OFF_B32 + (uint32_t)((t % 3) * G1_B32_STAGE);
        const uint32_t dstB = sb + G1_OFF_B16 + (uint32_t)((t & 1) * G1_A_STAGE);
#pragma unroll
        for (int j = 0; j < 2; j++) {
            int oc = vcol + j;
            float4 f0 = *(const float4*)(smem + (srcB - sb) + vrow * G1_PITCH_B32 + oc * 32);
            float4 f1 = *(const float4*)(smem + (srcB - sb) + vrow * G1_PITCH_B32 + oc * 32 + 16);
            uint2 p0 = cvt_f4(f0);
            uint2 p1 = cvt_f4(f1);
            *(uint4*)(smem + (dstB - sb) + vrow * G1_PITCH_A + oc * 16) =
                make_uint4(p0.x, p0.y, p1.x, p1.y);
        }
        __syncthreads();

        // compute stage t (2 ko steps of k16)
        const uint32_t stA = sb + G1_OFF_A + (uint32_t)((t % 3) * G1_A_STAGE);
#pragma unroll
        for (int ko = 0; ko < 2; ko++) {
            uint32_t ah[2][4];
#pragma unroll
            for (int mt = 0; mt < 2; mt++)
                ldsm_x4(ah[mt], stA + aOff + mt * 16 * G1_PITCH_A + ko * 32);
#pragma unroll
            for (int np = 0; np < 4; np++) {
                uint32_t bh[4];
                ldsm_x4(bh, dstB + bOff + np * 16 * G1_PITCH_A + ko * 32);
#pragma unroll
                for (int sub = 0; sub < 2; sub++)
#pragma unroll
                    for (int mt = 0; mt < 2; mt++)
                        mma_f16(acc[mt][np * 2 + sub], ah[mt], bh + sub * 2);
            }
        }

        // prefetch stage t+2 (slot of t-1, fully consumed); commit always
        if (t + 2 < NT) {
            load_stage(t + 2);
        } else {
            cp_commit();
        }
    }

    // epilogue -> H^T fp16, ldc = M_ALL
    const int l4 = lane >> 2;
    const int lp = lane & 3;
#pragma unroll
    for (int mt = 0; mt < 2; mt++) {
#pragma unroll
        for (int nt = 0; nt < 8; nt++) {
            const float* c = acc[mt][nt];
            long m = m0 + wm + mt * 16 + l4;
            long n = n0 + wn + nt * 8 + lp * 2;
            __half2 p0 = __float22half2_rn(make_float2(c[0], c[1]));
            __half2 p1 = __float22half2_rn(make_float2(c[2], c[3]));
            *(uint32_t*)(Ch + m * M_ALL + n) = *(uint32_t*)&p0;
            *(uint32_t*)(Ch + (m + 8) * M_ALL + n) = *(uint32_t*)&p1;
        }
    }
}

// ---------------- GEMM2 (R8 kernel, fp32 out) ----------------
__global__ __launch_bounds__(NTHREADS, 2)
void hgemm_f16(const __half* __restrict__ A, int lda,
               const __half* __restrict__ B, int ldb, long bStride,
               float* __restrict__ Cf, int ldc, long cStride, int K) {
    extern __shared__ char smem[];
    const uint32_t sb = smem_u32(smem);
    const int tid = threadIdx.x;
    const int lane = tid & 31;
    const int wid = tid >> 5;
    const int wm = (wid & 3) * 32;
    const int wn = (wid >> 2) * 64;

    const int m0 = blockIdx.y * BM;
    const int n0 = blockIdx.x * BN;
    const long bz = blockIdx.z;
    B += bz * bStride;

    const int cr = tid >> 3;
    const int cc = tid & 7;
    const uint32_t soBase = (uint32_t)(cc * 16);
    const int gcol = cc * 8;

    const uint32_t aOff = (uint32_t)((wm + (lane & 15)) * PITCHB + ((lane >> 4) << 4));
    const uint32_t bOff = (uint32_t)((wn + ((lane >> 4) << 3) + (lane & 7)) * PITCHB +
                                     (((lane >> 3) & 1) << 4));

    float acc[2][8][4];
#pragma unroll
    for (int mt = 0; mt < 2; mt++)
#pragma unroll
        for (int nt = 0; nt < 8; nt++)
#pragma unroll
            for (int q = 0; q < 4; q++) acc[mt][nt][q] = 0.0f;

    const int NT = K / BKB;

    auto load_stage = [&](int t) {
        const uint32_t st = sb + (uint32_t)((t % S_STAGES) * STAGEB);
        const int k0 = t * BKB + gcol;
#pragma unroll
        for (int j = 0; j < 4; j++) {
            int r = cr + j * 32;
            uint32_t so = (uint32_t)(r * PITCHB) + soBase;
            cp16(st + OFF_A + so, A + (size_t)(m0 + r) * lda + k0);
            cp16(st + OFF_B + so, B + (size_t)(n0 + r) * ldb + k0);
        }
        cp_commit();
    };

    load_stage(0);
    if (NT > 1) load_stage(1);

    for (int t = 0; t < NT; t++) {
        cp_wait<1>();
        __syncthreads();

        const uint32_t st = sb + (uint32_t)((t % S_STAGES) * STAGEB);

        uint32_t ah[2][2][4];
#pragma unroll
        for (int mt = 0; mt < 2; mt++)
            ldsm_x4(ah[0][mt], st + OFF_A + aOff + mt * 16 * PITCHB);

#pragma unroll
        for (int ko = 0; ko < 4; ko++) {
            const int cur = ko & 1, nxt = cur ^ 1;
            if (ko < 3) {
#pragma unroll
                for (int mt = 0; mt < 2; mt++)
                    ldsm_x4(ah[nxt][mt], st + OFF_A + aOff + mt * 16 * PITCHB + (ko + 1) * 32);
            }
#pragma unroll
            for (int np = 0; np < 4; np++) {
                uint32_t bh[4];
                ldsm_x4(bh, st + OFF_B + bOff + np * 16 * PITCHB + ko * 32);
#pragma unroll
                for (int sub = 0; sub < 2; sub++)
#pragma unroll
                    for (int mt = 0; mt < 2; mt++)
                        mma_f16(acc[mt][np * 2 + sub], ah[cur][mt], bh + sub * 2);
            }
        }

        __syncthreads();
        if (t + 2 < NT) {
            load_stage(t + 2);
        } else {
            cp_commit();
        }
    }

    const int l4 = lane >> 2;
    const int lp = lane & 3;
#pragma unroll
    for (int mt = 0; mt < 2; mt++) {
#pragma unroll
        for (int nt = 0; nt < 8; nt++) {
            const float* c = acc[mt][nt];
            long m = m0 + wm + mt * 16 + l4;
            long n = n0 + wn + nt * 8 + lp * 2;
            float* base = Cf + bz * cStride;
            *(float2*)(base + m * ldc + n) = make_float2(c[0], c[1]);
            *(float2*)(base + (m + 8) * ldc + n) = make_float2(c[2], c[3]);
        }
    }
}

// ---------------- launch ----------------
extern "C" void kernel_launch(void* const* d_in, const int* in_sizes, int n_in,
                              void* d_out, int out_size) {
    const float* x      = (const float*)d_in[0];
    const float* weight = (const float*)d_in[2];
    const float* adj    = (const float*)d_in[3];
    float* out          = (float*)d_out;

    __half *wth, *adjh, *h;
    cudaGetSymbolAddress((void**)&wth, g_wth);
    cudaGetSymbolAddress((void**)&adjh, g_adjh);
    cudaGetSymbolAddress((void**)&h, g_h);

    cudaFuncSetAttribute(gemm1_fused, cudaFuncAttributeMaxDynamicSharedMemorySize, G1_SMEM);
    cudaFuncSetAttribute(hgemm_f16, cudaFuncAttributeMaxDynamicSharedMemorySize, SMEM_TOTAL);

    cvt_small<<<320, 256>>>(adj, weight, adjh, wth);

    // GEMM1 fused: H^T = W^T @ X^T (X fp32 consumed directly)
    {
        dim3 grid(M_ALL / BN, D_OUT / BM, 1);   // (256, 2)
        gemm1_fused<<<grid, NTHREADS, G1_SMEM>>>(wth, x, h);
    }
    // GEMM2: Out[b] = adj @ H_b
    {
        dim3 grid(D_OUT / BN, N_NODES / BM, N_BATCH);
        hgemm_f16<<<grid, NTHREADS, SMEM_TOTAL>>>(
            adjh, N_NODES,
            h, M_ALL, (long)N_NODES,
            out, D_OUT, (long)(N_NODES * D_OUT),
            N_NODES);
    }
}